// round 1
// baseline (speedup 1.0000x reference)
#include <cuda_runtime.h>
#include <math.h>

#define BATCH   8
#define IN_CH   8
#define IMG     224
#define PATCHSZ 16
#define HGRID   14
#define LSEQ    1568            // 14*14*8
#define MROWS   12544           // BATCH*LSEQ
#define DM      768
#define DI      1536
#define DS      16
#define DR      48
#define NC      1000
#define DEPTH   4
#define EPS_LN  1e-5f

// ---------------- device scratch (static global mem; no runtime alloc) ----------------
__device__ float g_patch[(size_t)MROWS * 256];
__device__ float g_res  [(size_t)MROWS * DM];
__device__ float g_hid  [(size_t)MROWS * DM];
__device__ float g_hn   [(size_t)MROWS * DM];
__device__ float g_xz   [(size_t)MROWS * 2 * DI];
__device__ float g_xc   [(size_t)MROWS * DI];
__device__ float g_dbc  [(size_t)MROWS * 80];
__device__ float g_dt   [(size_t)MROWS * DI];
__device__ float g_y    [(size_t)MROWS * DI];
__device__ float g_pool [BATCH * DM];

// ---------------- helpers ----------------
__device__ __forceinline__ float warp_sum(float v) {
#pragma unroll
    for (int o = 16; o; o >>= 1) v += __shfl_xor_sync(0xffffffffu, v, o);
    return v;
}

// block of 256 threads, returns total in every thread. sh must be >= 8 floats.
__device__ __forceinline__ float blk_sum(float v, float* sh) {
    int lane = threadIdx.x & 31, w = threadIdx.x >> 5;
    v = warp_sum(v);
    __syncthreads();             // protect sh from previous use
    if (lane == 0) sh[w] = v;
    __syncthreads();
    float t = (lane < 8) ? sh[lane] : 0.0f;
#pragma unroll
    for (int o = 4; o; o >>= 1) t += __shfl_xor_sync(0xffffffffu, t, o);
    return __shfl_sync(0xffffffffu, t, 0);
}

// ---------------- im2col for patch embedding ----------------
// row = b*1568 + l,  l = (hg*14+wg)*8 + c,  col = p*16 + q
__global__ void k_im2col(const float* __restrict__ x, float* __restrict__ patch) {
    int row = blockIdx.x;
    int k   = threadIdx.x;          // 0..255
    int l  = row % LSEQ;
    int b  = row / LSEQ;
    int c  = l & 7;
    int hw = l >> 3;
    int wg = hw % HGRID;
    int hg = hw / HGRID;
    int p  = k >> 4;
    int q  = k & 15;
    float v = x[(((size_t)(b * IN_CH + c) * IMG) + (hg * PATCHSZ + p)) * IMG + (wg * PATCHSZ + q)];
    patch[(size_t)row * 256 + k] = v;
}

// ---------------- generic fp32 tiled GEMM: C[M,N] = A[M,K(lda)] * W[N,K]^T ----------------
// BM=BN=128, BK=16, 256 threads, 8x8 per thread. M must be multiple of 128, K multiple of 16.
__global__ void __launch_bounds__(256, 2)
k_gemm_nt(const float* __restrict__ A, int lda,
          const float* __restrict__ W,
          float* __restrict__ C,
          int Mdim, int Ndim, int K) {
    __shared__ float As[16][132];
    __shared__ float Ws[16][132];
    int bm = blockIdx.y * 128;
    int bn = blockIdx.x * 128;
    int tid = threadIdx.x;
    int tr = tid >> 4;          // 0..15
    int tc = tid & 15;          // 0..15

    float acc[8][8];
#pragma unroll
    for (int i = 0; i < 8; i++)
#pragma unroll
        for (int j = 0; j < 8; j++) acc[i][j] = 0.0f;

    for (int k0 = 0; k0 < K; k0 += 16) {
#pragma unroll
        for (int i = 0; i < 2; i++) {
            int f4 = tid + i * 256;          // 0..511
            int r  = f4 >> 2;                // 0..127
            int c4 = (f4 & 3) << 2;          // 0,4,8,12
            float4 av = *(const float4*)(A + (size_t)(bm + r) * lda + k0 + c4);
            As[c4 + 0][r] = av.x; As[c4 + 1][r] = av.y;
            As[c4 + 2][r] = av.z; As[c4 + 3][r] = av.w;
            float4 wv = make_float4(0.f, 0.f, 0.f, 0.f);
            if (bn + r < Ndim)
                wv = *(const float4*)(W + (size_t)(bn + r) * K + k0 + c4);
            Ws[c4 + 0][r] = wv.x; Ws[c4 + 1][r] = wv.y;
            Ws[c4 + 2][r] = wv.z; Ws[c4 + 3][r] = wv.w;
        }
        __syncthreads();
#pragma unroll
        for (int kk = 0; kk < 16; kk++) {
            float4 a0 = *(const float4*)&As[kk][tr * 8];
            float4 a1 = *(const float4*)&As[kk][tr * 8 + 4];
            float4 w0 = *(const float4*)&Ws[kk][tc * 8];
            float4 w1 = *(const float4*)&Ws[kk][tc * 8 + 4];
            float a[8] = {a0.x, a0.y, a0.z, a0.w, a1.x, a1.y, a1.z, a1.w};
            float w[8] = {w0.x, w0.y, w0.z, w0.w, w1.x, w1.y, w1.z, w1.w};
#pragma unroll
            for (int i = 0; i < 8; i++)
#pragma unroll
                for (int j = 0; j < 8; j++) acc[i][j] += a[i] * w[j];
        }
        __syncthreads();
    }

#pragma unroll
    for (int i = 0; i < 8; i++) {
        int m = bm + tr * 8 + i;
#pragma unroll
        for (int j = 0; j < 8; j += 4) {
            int n = bn + tc * 8 + j;
            if (n + 3 < Ndim) {
                float4 st = make_float4(acc[i][j], acc[i][j + 1], acc[i][j + 2], acc[i][j + 3]);
                *(float4*)(C + (size_t)m * Ndim + n) = st;
            } else {
#pragma unroll
                for (int q = 0; q < 4; q++)
                    if (n + q < Ndim) C[(size_t)m * Ndim + n + q] = acc[i][j + q];
            }
        }
    }
}

// ---------------- add patch bias + channel embed ----------------
__global__ void k_add_embed(float* __restrict__ hid, const float* __restrict__ pb,
                            const float* __restrict__ ce) {
    size_t idx = (size_t)blockIdx.x * 256 + threadIdx.x;
    if (idx >= (size_t)MROWS * DM) return;
    int d   = (int)(idx % DM);
    int row = (int)(idx / DM);
    int c   = (row % LSEQ) & 7;
    hid[idx] += pb[d] + ce[c * DM + d];
}

// ---------------- residual update + LayerNorm (width 768) ----------------
__global__ void k_resid_ln(const float* __restrict__ hid, float* __restrict__ res,
                           float* __restrict__ hn, const float* __restrict__ w,
                           const float* __restrict__ b, int first) {
    __shared__ float sh[8];
    int row = blockIdx.x;
    float v[3];
#pragma unroll
    for (int j = 0; j < 3; j++) {
        int c = threadIdx.x + j * 256;
        size_t idx = (size_t)row * DM + c;
        float r = first ? hid[idx] : (res[idx] + hid[idx]);
        res[idx] = r;
        v[j] = r;
    }
    float mean = blk_sum(v[0] + v[1] + v[2], sh) * (1.0f / DM);
    float sq = 0.f;
#pragma unroll
    for (int j = 0; j < 3; j++) { v[j] -= mean; sq += v[j] * v[j]; }
    float var = blk_sum(sq, sh) * (1.0f / DM);
    float iv = rsqrtf(var + EPS_LN);
#pragma unroll
    for (int j = 0; j < 3; j++) {
        int c = threadIdx.x + j * 256;
        hn[(size_t)row * DM + c] = v[j] * iv * w[c] + b[c];
    }
}

// ---------------- depthwise causal conv (width 4) + SiLU ----------------
__global__ void k_conv_silu(const float* __restrict__ xz, const float* __restrict__ cw,
                            const float* __restrict__ cb, float* __restrict__ xc) {
    size_t idx = (size_t)blockIdx.x * 256 + threadIdx.x;
    if (idx >= (size_t)MROWS * DI) return;
    int e   = (int)(idx % DI);
    int row = (int)(idx / DI);
    int l   = row % LSEQ;
    float acc = cb[e];
    const float* cwp = cw + e * 4;
    size_t base = (size_t)row * (2 * DI) + e;
#pragma unroll
    for (int k = 0; k < 4; k++) {
        int ls = l - 3 + k;
        if (ls >= 0) acc += xz[base + (size_t)(k - 3) * (2 * DI)] * cwp[k];
    }
    xc[idx] = acc / (1.0f + expf(-acc));
}

// ---------------- softplus(x + bias) in-place on dt ----------------
__global__ void k_softplus(float* __restrict__ dt, const float* __restrict__ dtb) {
    size_t idx = (size_t)blockIdx.x * 256 + threadIdx.x;
    if (idx >= (size_t)MROWS * DI) return;
    int e = (int)(idx % DI);
    float a = dt[idx] + dtb[e];
    dt[idx] = (a > 20.0f) ? a : log1pf(expf(a));
}

// ---------------- selective scan: 4 lanes per (b,d) channel, 4 states each ----------------
__global__ void k_scan(const float* __restrict__ dt, const float* __restrict__ xc,
                       const float* __restrict__ dbc, const float* __restrict__ Alog,
                       float* __restrict__ y) {
    int gid = blockIdx.x * 128 + threadIdx.x;   // 0..49151
    int ch  = gid >> 2;                         // 0..12287
    int ng  = gid & 3;                          // state group
    int b   = ch / DI;
    int d   = ch % DI;

    float A0 = -expf(Alog[d * DS + ng * 4 + 0]);
    float A1 = -expf(Alog[d * DS + ng * 4 + 1]);
    float A2 = -expf(Alog[d * DS + ng * 4 + 2]);
    float A3 = -expf(Alog[d * DS + ng * 4 + 3]);

    float h0 = 0.f, h1 = 0.f, h2 = 0.f, h3 = 0.f;
    const float* dbcb = dbc + (size_t)b * LSEQ * 80;
    int rowbase = b * LSEQ;

    for (int t = 0; t < LSEQ; t++) {
        int row = rowbase + t;
        float dtv = dt[(size_t)row * DI + d];
        float xv  = xc[(size_t)row * DI + d];
        float4 Bv = *(const float4*)(dbcb + (size_t)t * 80 + 48 + ng * 4);
        float4 Cv = *(const float4*)(dbcb + (size_t)t * 80 + 64 + ng * 4);
        float u = dtv * xv;
        h0 = __expf(dtv * A0) * h0 + u * Bv.x;
        h1 = __expf(dtv * A1) * h1 + u * Bv.y;
        h2 = __expf(dtv * A2) * h2 + u * Bv.z;
        h3 = __expf(dtv * A3) * h3 + u * Bv.w;
        float p = h0 * Cv.x + h1 * Cv.y + h2 * Cv.z + h3 * Cv.w;
        p += __shfl_xor_sync(0xffffffffu, p, 1);
        p += __shfl_xor_sync(0xffffffffu, p, 2);
        if (ng == 0) y[(size_t)row * DI + d] = p;
    }
}

// ---------------- y = LN(y + D*x) * silu(z)  (width 1536) ----------------
__global__ void k_ypost(float* __restrict__ y, const float* __restrict__ xc,
                        const float* __restrict__ xz, const float* __restrict__ Dp,
                        const float* __restrict__ snw, const float* __restrict__ snb) {
    __shared__ float sh[8];
    int row = blockIdx.x;
    float v[6];
#pragma unroll
    for (int j = 0; j < 6; j++) {
        int c = threadIdx.x + j * 256;
        size_t idx = (size_t)row * DI + c;
        v[j] = y[idx] + Dp[c] * xc[idx];
    }
    float s = 0.f;
#pragma unroll
    for (int j = 0; j < 6; j++) s += v[j];
    float mean = blk_sum(s, sh) * (1.0f / DI);
    float sq = 0.f;
#pragma unroll
    for (int j = 0; j < 6; j++) { v[j] -= mean; sq += v[j] * v[j]; }
    float var = blk_sum(sq, sh) * (1.0f / DI);
    float iv = rsqrtf(var + EPS_LN);
#pragma unroll
    for (int j = 0; j < 6; j++) {
        int c = threadIdx.x + j * 256;
        float nv = v[j] * iv * snw[c] + snb[c];
        float z = xz[(size_t)row * (2 * DI) + DI + c];
        y[(size_t)row * DI + c] = nv * (z / (1.0f + expf(-z)));
    }
}

// ---------------- mean-pool partial sums ----------------
__global__ void k_pool(const float* __restrict__ hn, float* __restrict__ pool) {
    int b = blockIdx.x;
    int chunk = blockIdx.y;      // 14 chunks of 112 tokens
#pragma unroll
    for (int j = 0; j < 3; j++) {
        int d = threadIdx.x + j * 256;
        float s = 0.f;
        int l0 = chunk * 112;
        for (int l = l0; l < l0 + 112; l++)
            s += hn[((size_t)(b * LSEQ + l)) * DM + d];
        atomicAdd(&pool[b * DM + d], s);
    }
}

// ---------------- head: out[b,cls] = mean(hf)·head_w[cls] + head_b ----------------
__global__ void k_head(const float* __restrict__ pool, const float* __restrict__ hw,
                       const float* __restrict__ hb, float* __restrict__ out) {
    int cls = blockIdx.x;
    int b   = threadIdx.x >> 5;     // 8 warps = 8 batches
    int lane = threadIdx.x & 31;
    float s = 0.f;
    for (int d = lane; d < DM; d += 32)
        s += pool[b * DM + d] * hw[(size_t)cls * DM + d];
    s = warp_sum(s);
    if (lane == 0)
        out[b * NC + cls] = s * (1.0f / (float)LSEQ) + hb[cls];
}

// ---------------- launch ----------------
extern "C" void kernel_launch(void* const* d_in, const int* in_sizes, int n_in,
                              void* d_out, int out_size) {
    const float* x      = (const float*)d_in[0];
    const float* pw     = (const float*)d_in[1];
    const float* pb     = (const float*)d_in[2];
    const float* ce     = (const float*)d_in[3];
    const float* nw     = (const float*)d_in[4];
    const float* nb     = (const float*)d_in[5];
    const float* ipw    = (const float*)d_in[6];
    const float* cw     = (const float*)d_in[7];
    const float* cb     = (const float*)d_in[8];
    const float* xpw    = (const float*)d_in[9];
    const float* dtw    = (const float*)d_in[10];
    const float* dtb    = (const float*)d_in[11];
    const float* alog   = (const float*)d_in[12];
    const float* Dp     = (const float*)d_in[13];
    const float* snw    = (const float*)d_in[14];
    const float* snb    = (const float*)d_in[15];
    const float* opw    = (const float*)d_in[16];
    const float* nfw    = (const float*)d_in[17];
    const float* nfb    = (const float*)d_in[18];
    const float* hw     = (const float*)d_in[19];
    const float* hb     = (const float*)d_in[20];
    float* out = (float*)d_out;

    float *patch, *res, *hid, *hn, *xz, *xc, *dbc, *dtbuf, *ybuf, *pool;
    cudaGetSymbolAddress((void**)&patch, g_patch);
    cudaGetSymbolAddress((void**)&res,   g_res);
    cudaGetSymbolAddress((void**)&hid,   g_hid);
    cudaGetSymbolAddress((void**)&hn,    g_hn);
    cudaGetSymbolAddress((void**)&xz,    g_xz);
    cudaGetSymbolAddress((void**)&xc,    g_xc);
    cudaGetSymbolAddress((void**)&dbc,   g_dbc);
    cudaGetSymbolAddress((void**)&dtbuf, g_dt);
    cudaGetSymbolAddress((void**)&ybuf,  g_y);
    cudaGetSymbolAddress((void**)&pool,  g_pool);

    const int ew_di = (int)(((size_t)MROWS * DI + 255) / 256);     // 75264
    const int ew_dm = (int)(((size_t)MROWS * DM + 255) / 256);     // 37632

    // patch embedding
    k_im2col<<<MROWS, 256>>>(x, patch);
    k_gemm_nt<<<dim3(DM / 128, MROWS / 128), 256>>>(patch, 256, pw, hid, MROWS, DM, 256);
    k_add_embed<<<ew_dm, 256>>>(hid, pb, ce);

    for (int i = 0; i < DEPTH; i++) {
        k_resid_ln<<<MROWS, 256>>>(hid, res, hn, nw + i * DM, nb + i * DM, i == 0 ? 1 : 0);
        k_gemm_nt<<<dim3(2 * DI / 128, MROWS / 128), 256>>>(
            hn, DM, ipw + (size_t)i * 2 * DI * DM, xz, MROWS, 2 * DI, DM);
        k_conv_silu<<<ew_di, 256>>>(xz, cw + (size_t)i * DI * 4, cb + i * DI, xc);
        k_gemm_nt<<<dim3(1, MROWS / 128), 256>>>(
            xc, DI, xpw + (size_t)i * 80 * DI, dbc, MROWS, 80, DI);
        k_gemm_nt<<<dim3(DI / 128, MROWS / 128), 256>>>(
            dbc, 80, dtw + (size_t)i * DI * DR, dtbuf, MROWS, DI, DR);
        k_softplus<<<ew_di, 256>>>(dtbuf, dtb + i * DI);
        k_scan<<<(BATCH * DI * 4) / 128, 128>>>(dtbuf, xc, dbc, alog + (size_t)i * DI * DS, ybuf);
        k_ypost<<<MROWS, 256>>>(ybuf, xc, xz, Dp + i * DI, snw + i * DI, snb + i * DI);
        k_gemm_nt<<<dim3(DM / 128, MROWS / 128), 256>>>(
            ybuf, DI, opw + (size_t)i * DM * DI, hid, MROWS, DM, DI);
    }

    // final residual + LN + pool + head
    k_resid_ln<<<MROWS, 256>>>(hid, res, hn, nfw, nfb, 0);
    cudaMemsetAsync(pool, 0, BATCH * DM * sizeof(float));
    k_pool<<<dim3(BATCH, 14), 256>>>(hn, pool);
    k_head<<<NC, 256>>>(pool, hw, hb, out);
}

// round 4
// speedup vs baseline: 1.4295x; 1.4295x over previous
#include <cuda_runtime.h>
#include <cuda_bf16.h>
#include <math.h>
#include <stdint.h>

#define BATCH   8
#define IN_CH   8
#define IMG     224
#define PATCHSZ 16
#define HGRID   14
#define LSEQ    1568            // 14*14*8
#define MROWS   12544           // BATCH*LSEQ = 98*128
#define DM      768
#define DI      1536
#define DS      16
#define DR      48
#define NC      1000
#define DEPTH   4
#define EPS_LN  1e-5f

// ---------------- device scratch (static global mem; no runtime alloc) ----------------
__device__ float g_patch[(size_t)MROWS * 256];
__device__ float g_res  [(size_t)MROWS * DM];
__device__ float g_hid  [(size_t)MROWS * DM];
__device__ float g_hn   [(size_t)MROWS * DM];
__device__ float g_xz   [(size_t)MROWS * 2 * DI];
__device__ float g_xc   [(size_t)MROWS * DI];
__device__ float g_dbc  [(size_t)MROWS * 80];
__device__ float g_dt   [(size_t)MROWS * DI];
__device__ float g_y    [(size_t)MROWS * DI];
__device__ float g_pool [BATCH * DM];

// ---------------- helpers ----------------
__device__ __forceinline__ float warp_sum(float v) {
#pragma unroll
    for (int o = 16; o; o >>= 1) v += __shfl_xor_sync(0xffffffffu, v, o);
    return v;
}

__device__ __forceinline__ float blk_sum(float v, float* sh) {
    int lane = threadIdx.x & 31, w = threadIdx.x >> 5;
    v = warp_sum(v);
    __syncthreads();
    if (lane == 0) sh[w] = v;
    __syncthreads();
    float t = (lane < 8) ? sh[lane] : 0.0f;
#pragma unroll
    for (int o = 4; o; o >>= 1) t += __shfl_xor_sync(0xffffffffu, t, o);
    return __shfl_sync(0xffffffffu, t, 0);
}

__device__ __forceinline__ uint32_t smem_u32(const void* p) {
    uint32_t a;
    asm("{ .reg .u64 t; cvta.to.shared.u64 t, %1; cvt.u32.u64 %0, t; }" : "=r"(a) : "l"(p));
    return a;
}

__device__ __forceinline__ void ldmx4(uint32_t addr, uint32_t& r0, uint32_t& r1,
                                      uint32_t& r2, uint32_t& r3) {
    asm volatile("ldmatrix.sync.aligned.m8n8.x4.shared.b16 {%0,%1,%2,%3}, [%4];"
                 : "=r"(r0), "=r"(r1), "=r"(r2), "=r"(r3) : "r"(addr));
}

__device__ __forceinline__ void mma16816(float* c, const uint32_t* a, uint32_t b0, uint32_t b1) {
    asm volatile(
        "mma.sync.aligned.m16n8k16.row.col.f32.bf16.bf16.f32 "
        "{%0,%1,%2,%3}, {%4,%5,%6,%7}, {%8,%9}, {%0,%1,%2,%3};"
        : "+f"(c[0]), "+f"(c[1]), "+f"(c[2]), "+f"(c[3])
        : "r"(a[0]), "r"(a[1]), "r"(a[2]), "r"(a[3]), "r"(b0), "r"(b1));
}

__device__ __forceinline__ uint32_t pack_hi(float x, float y, float& rx, float& ry) {
    __nv_bfloat162 p = __floats2bfloat162_rn(x, y);
    rx = x - __bfloat162float(p.x);
    ry = y - __bfloat162float(p.y);
    return *(uint32_t*)&p;
}
__device__ __forceinline__ uint32_t pack_lo(float x, float y) {
    __nv_bfloat162 p = __floats2bfloat162_rn(x, y);
    return *(uint32_t*)&p;
}

// ============ HMMA GEMM: C[M,N] = A[M,K(lda)] * W[N,K]^T ============
// grid = (ceil(N/128), M/128), 256 threads (8 warps: warp_m=wid&1, warp_n=wid>>1).
// bf16-split 3-product emulation, fp32 accumulate. BK=32.
#define TSTRIDE 40    // halfs per SMEM row (padded, conflict-free for ldmatrix)

__global__ void __launch_bounds__(256, 2)
k_gemm_mma(const float* __restrict__ A, int lda,
           const float* __restrict__ W,
           float* __restrict__ C,
           int Ndim, int K) {
    __shared__ __align__(16) __nv_bfloat16 sAh[128 * TSTRIDE];
    __shared__ __align__(16) __nv_bfloat16 sAl[128 * TSTRIDE];
    __shared__ __align__(16) __nv_bfloat16 sBh[128 * TSTRIDE];
    __shared__ __align__(16) __nv_bfloat16 sBl[128 * TSTRIDE];

    int tid  = threadIdx.x;
    int wid  = tid >> 5;
    int lane = tid & 31;
    int bm = blockIdx.y * 128;
    int bn = blockIdx.x * 128;
    int warp_m = wid & 1;        // 0..1  (64 rows each)
    int warp_n = wid >> 1;       // 0..3  (32 cols each)

    float acc[4][4][4];
#pragma unroll
    for (int i = 0; i < 4; i++)
#pragma unroll
        for (int j = 0; j < 4; j++)
#pragma unroll
            for (int q = 0; q < 4; q++) acc[i][j][q] = 0.0f;

    // loader mapping: thread t handles row t/2, 16 k-cols starting at (t&1)*16
    int lrow  = tid >> 1;
    int lcb   = (tid & 1) * 16;

    // ldmatrix base addresses (per-lane), reused each chunk/k-step
    int arow = warp_m * 64 + (lane & 15);
    int brow = warp_n * 32 + (lane & 15);
    int kgrp = (lane >> 4) * 8;          // 0 or 8 halfs

    uint32_t aAh = smem_u32(sAh), aAl = smem_u32(sAl);
    uint32_t aBh = smem_u32(sBh), aBl = smem_u32(sBl);

    int nchunks = (K + 31) >> 5;

    for (int c = 0; c < nchunks; c++) {
        int k0 = c * 32;
        // ---------- load + split + store ----------
#pragma unroll
        for (int i = 0; i < 4; i++) {
            int kc = k0 + lcb + i * 4;
            float4 av = make_float4(0.f, 0.f, 0.f, 0.f);
            float4 wv = make_float4(0.f, 0.f, 0.f, 0.f);
            if (kc < K) {
                av = *(const float4*)(A + (size_t)(bm + lrow) * lda + kc);
                if (bn + lrow < Ndim)
                    wv = *(const float4*)(W + (size_t)(bn + lrow) * K + kc);
            }
            float rx, ry, rz, rw;
            uint32_t h0 = pack_hi(av.x, av.y, rx, ry);
            uint32_t h1 = pack_hi(av.z, av.w, rz, rw);
            int so = lrow * TSTRIDE + lcb + i * 4;
            *(uint2*)(sAh + so) = make_uint2(h0, h1);
            *(uint2*)(sAl + so) = make_uint2(pack_lo(rx, ry), pack_lo(rz, rw));
            h0 = pack_hi(wv.x, wv.y, rx, ry);
            h1 = pack_hi(wv.z, wv.w, rz, rw);
            *(uint2*)(sBh + so) = make_uint2(h0, h1);
            *(uint2*)(sBl + so) = make_uint2(pack_lo(rx, ry), pack_lo(rz, rw));
        }
        __syncthreads();

        // ---------- MMA: 2 k-steps of 16 ----------
#pragma unroll
        for (int ks = 0; ks < 2; ks++) {
            int koff = ks * 16 + kgrp;
            uint32_t ah[4][4], al[4][4];
#pragma unroll
            for (int mt = 0; mt < 4; mt++) {
                uint32_t off = (uint32_t)((arow + mt * 16) * TSTRIDE + koff) * 2;
                ldmx4(aAh + off, ah[mt][0], ah[mt][1], ah[mt][2], ah[mt][3]);
                ldmx4(aAl + off, al[mt][0], al[mt][1], al[mt][2], al[mt][3]);
            }
            uint32_t bh[2][4], bl[2][4];
#pragma unroll
            for (int ng = 0; ng < 2; ng++) {
                uint32_t off = (uint32_t)((brow + ng * 16) * TSTRIDE + koff) * 2;
                ldmx4(aBh + off, bh[ng][0], bh[ng][1], bh[ng][2], bh[ng][3]);
                ldmx4(aBl + off, bl[ng][0], bl[ng][1], bl[ng][2], bl[ng][3]);
            }
#pragma unroll
            for (int mt = 0; mt < 4; mt++)
#pragma unroll
                for (int nt = 0; nt < 4; nt++) {
                    int ng = nt >> 1, sel = nt & 1;
                    // Ah*Bh + Ah*Bl + Al*Bh
                    mma16816(acc[mt][nt], ah[mt], bh[ng][sel], bh[ng][sel + 2]);
                    mma16816(acc[mt][nt], ah[mt], bl[ng][sel], bl[ng][sel + 2]);
                    mma16816(acc[mt][nt], al[mt], bh[ng][sel], bh[ng][sel + 2]);
                }
        }
        __syncthreads();
    }

    // ---------- epilogue ----------
    int rg = lane >> 2;          // 0..7
    int cg = (lane & 3) * 2;     // 0,2,4,6
#pragma unroll
    for (int mt = 0; mt < 4; mt++) {
        int m = bm + warp_m * 64 + mt * 16 + rg;
#pragma unroll
        for (int nt = 0; nt < 4; nt++) {
            int n = bn + warp_n * 32 + nt * 8 + cg;
            if (n < Ndim) {
                *(float2*)(C + (size_t)m * Ndim + n) =
                    make_float2(acc[mt][nt][0], acc[mt][nt][1]);
                *(float2*)(C + (size_t)(m + 8) * Ndim + n) =
                    make_float2(acc[mt][nt][2], acc[mt][nt][3]);
            }
        }
    }
}

// ---------------- im2col for patch embedding ----------------
__global__ void k_im2col(const float* __restrict__ x, float* __restrict__ patch) {
    int row = blockIdx.x;
    int k   = threadIdx.x;
    int l  = row % LSEQ;
    int b  = row / LSEQ;
    int c  = l & 7;
    int hw = l >> 3;
    int wg = hw % HGRID;
    int hg = hw / HGRID;
    int p  = k >> 4;
    int q  = k & 15;
    float v = x[(((size_t)(b * IN_CH + c) * IMG) + (hg * PATCHSZ + p)) * IMG + (wg * PATCHSZ + q)];
    patch[(size_t)row * 256 + k] = v;
}

// ---------------- add patch bias + channel embed ----------------
__global__ void k_add_embed(float* __restrict__ hid, const float* __restrict__ pb,
                            const float* __restrict__ ce) {
    size_t idx = (size_t)blockIdx.x * 256 + threadIdx.x;
    if (idx >= (size_t)MROWS * DM) return;
    int d   = (int)(idx % DM);
    int row = (int)(idx / DM);
    int c   = (row % LSEQ) & 7;
    hid[idx] += pb[d] + ce[c * DM + d];
}

// ---------------- residual update + LayerNorm (width 768) ----------------
__global__ void k_resid_ln(const float* __restrict__ hid, float* __restrict__ res,
                           float* __restrict__ hn, const float* __restrict__ w,
                           const float* __restrict__ b, int first) {
    __shared__ float sh[8];
    int row = blockIdx.x;
    float v[3];
#pragma unroll
    for (int j = 0; j < 3; j++) {
        int c = threadIdx.x + j * 256;
        size_t idx = (size_t)row * DM + c;
        float r = first ? hid[idx] : (res[idx] + hid[idx]);
        res[idx] = r;
        v[j] = r;
    }
    float mean = blk_sum(v[0] + v[1] + v[2], sh) * (1.0f / DM);
    float sq = 0.f;
#pragma unroll
    for (int j = 0; j < 3; j++) { v[j] -= mean; sq += v[j] * v[j]; }
    float var = blk_sum(sq, sh) * (1.0f / DM);
    float iv = rsqrtf(var + EPS_LN);
#pragma unroll
    for (int j = 0; j < 3; j++) {
        int c = threadIdx.x + j * 256;
        hn[(size_t)row * DM + c] = v[j] * iv * w[c] + b[c];
    }
}

// ---------------- depthwise causal conv (width 4) + SiLU ----------------
__global__ void k_conv_silu(const float* __restrict__ xz, const float* __restrict__ cw,
                            const float* __restrict__ cb, float* __restrict__ xc) {
    size_t idx = (size_t)blockIdx.x * 256 + threadIdx.x;
    if (idx >= (size_t)MROWS * DI) return;
    int e   = (int)(idx % DI);
    int row = (int)(idx / DI);
    int l   = row % LSEQ;
    float acc = cb[e];
    const float* cwp = cw + e * 4;
    size_t base = (size_t)row * (2 * DI) + e;
#pragma unroll
    for (int k = 0; k < 4; k++) {
        int ls = l - 3 + k;
        if (ls >= 0) acc += xz[base + (size_t)(k - 3) * (2 * DI)] * cwp[k];
    }
    xc[idx] = acc / (1.0f + expf(-acc));
}

// ---------------- softplus(x + bias) in-place on dt ----------------
__global__ void k_softplus(float* __restrict__ dt, const float* __restrict__ dtb) {
    size_t idx = (size_t)blockIdx.x * 256 + threadIdx.x;
    if (idx >= (size_t)MROWS * DI) return;
    int e = (int)(idx % DI);
    float a = dt[idx] + dtb[e];
    dt[idx] = (a > 20.0f) ? a : log1pf(expf(a));
}

// ---------------- selective scan ----------------
__global__ void k_scan(const float* __restrict__ dt, const float* __restrict__ xc,
                       const float* __restrict__ dbc, const float* __restrict__ Alog,
                       float* __restrict__ y) {
    int gid = blockIdx.x * 128 + threadIdx.x;
    int ch  = gid >> 2;
    int ng  = gid & 3;
    int b   = ch / DI;
    int d   = ch % DI;

    float A0 = -expf(Alog[d * DS + ng * 4 + 0]);
    float A1 = -expf(Alog[d * DS + ng * 4 + 1]);
    float A2 = -expf(Alog[d * DS + ng * 4 + 2]);
    float A3 = -expf(Alog[d * DS + ng * 4 + 3]);

    float h0 = 0.f, h1 = 0.f, h2 = 0.f, h3 = 0.f;
    const float* dbcb = dbc + (size_t)b * LSEQ * 80;
    int rowbase = b * LSEQ;

    for (int t = 0; t < LSEQ; t++) {
        int row = rowbase + t;
        float dtv = dt[(size_t)row * DI + d];
        float xv  = xc[(size_t)row * DI + d];
        float4 Bv = *(const float4*)(dbcb + (size_t)t * 80 + 48 + ng * 4);
        float4 Cv = *(const float4*)(dbcb + (size_t)t * 80 + 64 + ng * 4);
        float u = dtv * xv;
        h0 = __expf(dtv * A0) * h0 + u * Bv.x;
        h1 = __expf(dtv * A1) * h1 + u * Bv.y;
        h2 = __expf(dtv * A2) * h2 + u * Bv.z;
        h3 = __expf(dtv * A3) * h3 + u * Bv.w;
        float p = h0 * Cv.x + h1 * Cv.y + h2 * Cv.z + h3 * Cv.w;
        p += __shfl_xor_sync(0xffffffffu, p, 1);
        p += __shfl_xor_sync(0xffffffffu, p, 2);
        if (ng == 0) y[(size_t)row * DI + d] = p;
    }
}

// ---------------- y = LN(y + D*x) * silu(z)  (width 1536) ----------------
__global__ void k_ypost(float* __restrict__ y, const float* __restrict__ xc,
                        const float* __restrict__ xz, const float* __restrict__ Dp,
                        const float* __restrict__ snw, const float* __restrict__ snb) {
    __shared__ float sh[8];
    int row = blockIdx.x;
    float v[6];
#pragma unroll
    for (int j = 0; j < 6; j++) {
        int c = threadIdx.x + j * 256;
        size_t idx = (size_t)row * DI + c;
        v[j] = y[idx] + Dp[c] * xc[idx];
    }
    float s = 0.f;
#pragma unroll
    for (int j = 0; j < 6; j++) s += v[j];
    float mean = blk_sum(s, sh) * (1.0f / DI);
    float sq = 0.f;
#pragma unroll
    for (int j = 0; j < 6; j++) { v[j] -= mean; sq += v[j] * v[j]; }
    float var = blk_sum(sq, sh) * (1.0f / DI);
    float iv = rsqrtf(var + EPS_LN);
#pragma unroll
    for (int j = 0; j < 6; j++) {
        int c = threadIdx.x + j * 256;
        float nv = v[j] * iv * snw[c] + snb[c];
        float z = xz[(size_t)row * (2 * DI) + DI + c];
        y[(size_t)row * DI + c] = nv * (z / (1.0f + expf(-z)));
    }
}

// ---------------- mean-pool partial sums ----------------
__global__ void k_pool(const float* __restrict__ hn, float* __restrict__ pool) {
    int b = blockIdx.x;
    int chunk = blockIdx.y;
#pragma unroll
    for (int j = 0; j < 3; j++) {
        int d = threadIdx.x + j * 256;
        float s = 0.f;
        int l0 = chunk * 112;
        for (int l = l0; l < l0 + 112; l++)
            s += hn[((size_t)(b * LSEQ + l)) * DM + d];
        atomicAdd(&pool[b * DM + d], s);
    }
}

// ---------------- head ----------------
__global__ void k_head(const float* __restrict__ pool, const float* __restrict__ hw,
                       const float* __restrict__ hb, float* __restrict__ out) {
    int cls = blockIdx.x;
    int b   = threadIdx.x >> 5;
    int lane = threadIdx.x & 31;
    float s = 0.f;
    for (int d = lane; d < DM; d += 32)
        s += pool[b * DM + d] * hw[(size_t)cls * DM + d];
    s = warp_sum(s);
    if (lane == 0)
        out[b * NC + cls] = s * (1.0f / (float)LSEQ) + hb[cls];
}

// ---------------- launch ----------------
extern "C" void kernel_launch(void* const* d_in, const int* in_sizes, int n_in,
                              void* d_out, int out_size) {
    const float* x      = (const float*)d_in[0];
    const float* pw     = (const float*)d_in[1];
    const float* pb     = (const float*)d_in[2];
    const float* ce     = (const float*)d_in[3];
    const float* nw     = (const float*)d_in[4];
    const float* nb     = (const float*)d_in[5];
    const float* ipw    = (const float*)d_in[6];
    const float* cw     = (const float*)d_in[7];
    const float* cb     = (const float*)d_in[8];
    const float* xpw    = (const float*)d_in[9];
    const float* dtw    = (const float*)d_in[10];
    const float* dtb    = (const float*)d_in[11];
    const float* alog   = (const float*)d_in[12];
    const float* Dp     = (const float*)d_in[13];
    const float* snw    = (const float*)d_in[14];
    const float* snb    = (const float*)d_in[15];
    const float* opw    = (const float*)d_in[16];
    const float* nfw    = (const float*)d_in[17];
    const float* nfb    = (const float*)d_in[18];
    const float* hw     = (const float*)d_in[19];
    const float* hb     = (const float*)d_in[20];
    float* out = (float*)d_out;

    float *patch, *res, *hid, *hn, *xz, *xc, *dbc, *dtbuf, *ybuf, *pool;
    cudaGetSymbolAddress((void**)&patch, g_patch);
    cudaGetSymbolAddress((void**)&res,   g_res);
    cudaGetSymbolAddress((void**)&hid,   g_hid);
    cudaGetSymbolAddress((void**)&hn,    g_hn);
    cudaGetSymbolAddress((void**)&xz,    g_xz);
    cudaGetSymbolAddress((void**)&xc,    g_xc);
    cudaGetSymbolAddress((void**)&dbc,   g_dbc);
    cudaGetSymbolAddress((void**)&dtbuf, g_dt);
    cudaGetSymbolAddress((void**)&ybuf,  g_y);
    cudaGetSymbolAddress((void**)&pool,  g_pool);

    const int ew_di = (int)(((size_t)MROWS * DI + 255) / 256);
    const int ew_dm = (int)(((size_t)MROWS * DM + 255) / 256);
    const int MB = MROWS / 128;   // 98

    // patch embedding
    k_im2col<<<MROWS, 256>>>(x, patch);
    k_gemm_mma<<<dim3(DM / 128, MB), 256>>>(patch, 256, pw, hid, DM, 256);
    k_add_embed<<<ew_dm, 256>>>(hid, pb, ce);

    for (int i = 0; i < DEPTH; i++) {
        k_resid_ln<<<MROWS, 256>>>(hid, res, hn, nw + i * DM, nb + i * DM, i == 0 ? 1 : 0);
        k_gemm_mma<<<dim3(2 * DI / 128, MB), 256>>>(
            hn, DM, ipw + (size_t)i * 2 * DI * DM, xz, 2 * DI, DM);
        k_conv_silu<<<ew_di, 256>>>(xz, cw + (size_t)i * DI * 4, cb + i * DI, xc);
        k_gemm_mma<<<dim3(1, MB), 256>>>(
            xc, DI, xpw + (size_t)i * 80 * DI, dbc, 80, DI);
        k_gemm_mma<<<dim3(DI / 128, MB), 256>>>(
            dbc, 80, dtw + (size_t)i * DI * DR, dtbuf, DI, DR);
        k_softplus<<<ew_di, 256>>>(dtbuf, dtb + i * DI);
        k_scan<<<(BATCH * DI * 4) / 128, 128>>>(dtbuf, xc, dbc, alog + (size_t)i * DI * DS, ybuf);
        k_ypost<<<MROWS, 256>>>(ybuf, xc, xz, Dp + i * DI, snw + i * DI, snb + i * DI);
        k_gemm_mma<<<dim3(DM / 128, MB), 256>>>(
            ybuf, DI, opw + (size_t)i * DM * DI, hid, DM, DI);
    }

    // final residual + LN + pool + head
    k_resid_ln<<<MROWS, 256>>>(hid, res, hn, nfw, nfb, 0);
    cudaMemsetAsync(pool, 0, BATCH * DM * sizeof(float));
    k_pool<<<dim3(BATCH, 14), 256>>>(hn, pool);
    k_head<<<NC, 256>>>(pool, hw, hb, out);
}